// round 7
// baseline (speedup 1.0000x reference)
#include <cuda_runtime.h>
#include <cstdint>

#define N_NODES 50000
#define N_EDGES 800000
#define IN_DIM  128
#define OUT_DIM 128
#define EDGE_DIM 64

typedef unsigned long long u64;

// Scratch for node projections (allocation-free per harness rules).
__device__ __align__(16) float g_HU[(size_t)N_NODES * OUT_DIM];
__device__ __align__(16) float g_HW[(size_t)N_NODES * OUT_DIM];
__device__ int g_idx_is64;

__device__ __forceinline__ u64 pack2(float lo, float hi) {
    u64 r; asm("mov.b64 %0, {%1, %2};" : "=l"(r) : "f"(lo), "f"(hi)); return r;
}
__device__ __forceinline__ void fma2(u64& d, u64 a, u64 b) {
    asm("fma.rn.f32x2 %0, %1, %2, %3;" : "=l"(d) : "l"(a), "l"(b), "l"(d));
}
__device__ __forceinline__ float2 unpack2(u64 v) {
    float2 f; asm("mov.b64 {%0, %1}, %2;" : "=f"(f.x), "=f"(f.y) : "l"(v)); return f;
}

__device__ __forceinline__ int fetch_idx(const int* __restrict__ ei32,
                                         int is64, size_t pos) {
    int v = is64 ? ei32[2 * pos] : ei32[pos];
    v = v < 0 ? 0 : (v >= N_NODES ? N_NODES - 1 : v);
    return v;
}

// ---------------------------------------------------------------------------
// Node projection (both W_hu and W_hw via blockIdx.y) — proven R3 kernel.
// Block (0,0) additionally performs index-dtype detection (edge kernel
// launches strictly after, so the write is visible).
// ---------------------------------------------------------------------------
__global__ __launch_bounds__(256, 2)
void node_proj_kernel(const float* __restrict__ h,
                      const float* __restrict__ Whu,
                      const float* __restrict__ Whw,
                      const int* __restrict__ ei32)
{
    __shared__ __align__(16) float Wsh[32][132];
    __shared__ __align__(16) float Hsh[32][132];

    if (blockIdx.x == 0 && blockIdx.y == 0 && threadIdx.x == 0) {
        int all_zero = 1;
        for (int i = 0; i < 256; ++i)
            if (ei32[2 * i + 1] != 0) { all_zero = 0; break; }
        g_idx_is64 = all_zero;
    }

    const float* __restrict__ W   = blockIdx.y ? Whw : Whu;
    float*       __restrict__ dst = blockIdx.y ? g_HW : g_HU;

    const int tid = threadIdx.x;
    const int tx  = tid & 31;
    const int ty  = tid >> 5;
    const int n0  = blockIdx.x * 128;

    u64 acc[8][4];
#pragma unroll
    for (int p = 0; p < 8; ++p)
#pragma unroll
        for (int j = 0; j < 4; ++j) acc[p][j] = 0ULL;

#pragma unroll 1
    for (int s = 0; s < 4; ++s) {
        __syncthreads();
#pragma unroll
        for (int it = 0; it < 4; ++it) {
            int idx = it * 256 + tid;
            int o   = idx >> 3;
            int kq  = idx & 7;
            float4 w = *reinterpret_cast<const float4*>(W + (size_t)o * IN_DIM + s * 32 + kq * 4);
            Wsh[kq * 4 + 0][o] = w.x; Wsh[kq * 4 + 1][o] = w.y;
            Wsh[kq * 4 + 2][o] = w.z; Wsh[kq * 4 + 3][o] = w.w;
        }
#pragma unroll
        for (int it = 0; it < 4; ++it) {
            int idx = it * 256 + tid;
            int ln  = idx >> 3;
            int kq  = idx & 7;
            int n   = n0 + ln;
            float4 v = make_float4(0.f, 0.f, 0.f, 0.f);
            if (n < N_NODES)
                v = *reinterpret_cast<const float4*>(h + (size_t)n * IN_DIM + s * 32 + kq * 4);
            Hsh[kq * 4 + 0][ln] = v.x; Hsh[kq * 4 + 1][ln] = v.y;
            Hsh[kq * 4 + 2][ln] = v.z; Hsh[kq * 4 + 3][ln] = v.w;
        }
        __syncthreads();

#pragma unroll
        for (int k = 0; k < 32; ++k) {
            float4 w = *reinterpret_cast<const float4*>(&Wsh[k][tx * 4]);
            u64 w2[4];
            w2[0] = pack2(w.x, w.x); w2[1] = pack2(w.y, w.y);
            w2[2] = pack2(w.z, w.z); w2[3] = pack2(w.w, w.w);
            u64 ev[8];
#pragma unroll
            for (int q = 0; q < 4; ++q) {
                ulonglong2 ep = *reinterpret_cast<const ulonglong2*>(&Hsh[k][ty * 16 + q * 4]);
                ev[2 * q] = ep.x; ev[2 * q + 1] = ep.y;
            }
#pragma unroll
            for (int p = 0; p < 8; ++p)
#pragma unroll
                for (int j = 0; j < 4; ++j)
                    fma2(acc[p][j], ev[p], w2[j]);
        }
    }

#pragma unroll
    for (int p = 0; p < 8; ++p) {
        int na = n0 + ty * 16 + 2 * p;
        float2 v0 = unpack2(acc[p][0]), v1 = unpack2(acc[p][1]);
        float2 v2 = unpack2(acc[p][2]), v3 = unpack2(acc[p][3]);
        if (na < N_NODES)
            *reinterpret_cast<float4*>(dst + (size_t)na * OUT_DIM + tx * 4) =
                make_float4(v0.x, v1.x, v2.x, v3.x);
        if (na + 1 < N_NODES)
            *reinterpret_cast<float4*>(dst + (size_t)(na + 1) * OUT_DIM + tx * 4) =
                make_float4(v0.y, v1.y, v2.y, v3.y);
    }
}

// ---------------------------------------------------------------------------
// Fused edge kernel v3: block tile 128 edges x 64 outs, occupancy 3.
// W stored PRE-DUPLICATED as u64 pairs (no pack movs in mainloop);
// Esh double-buffered (one __syncthreads per stage).
// Thread tile 8 edges x 4 outs. Per-k: 2 LDS.128 (w2) + 2 LDS.128 (ev) + 16 fma2.
// ---------------------------------------------------------------------------
__global__ __launch_bounds__(256, 3)
void edge_kernel(const float* __restrict__ e,
                 const int* __restrict__ ei32,
                 const float* __restrict__ We,
                 float* __restrict__ out,
                 int tile_base)
{
    __shared__ __align__(16) u64   Wd[EDGE_DIM][66];     // [k][o] dup pairs  33.8KB
    __shared__ __align__(16) float Esh[2][16][132];      // double-buffered   16.9KB

    const int tid  = threadIdx.x;
    const int tx   = tid & 15;   // outs: oh + tx*4 .. +3
    const int ty   = tid >> 4;   // edges: ty*8 .. ty*8+7
    const int e0   = (tile_base + blockIdx.x) * 128;
    const int oh   = blockIdx.y * 64;
    const int is64 = g_idx_is64;

    // One-time W fill: We[oh+o][k] -> Wd[k][o] duplicated.
#pragma unroll
    for (int it = 0; it < 4; ++it) {
        int idx = it * 256 + tid;       // 0..1023
        int o   = idx & 63;
        int kq  = idx >> 6;             // 0..15
        float4 w = *reinterpret_cast<const float4*>(
            We + (size_t)(oh + o) * EDGE_DIM + kq * 4);
        Wd[kq * 4 + 0][o] = pack2(w.x, w.x);
        Wd[kq * 4 + 1][o] = pack2(w.y, w.y);
        Wd[kq * 4 + 2][o] = pack2(w.z, w.z);
        Wd[kq * 4 + 3][o] = pack2(w.w, w.w);
    }

    u64 acc[4][4];
#pragma unroll
    for (int p = 0; p < 4; ++p)
#pragma unroll
        for (int j = 0; j < 4; ++j) acc[p][j] = 0ULL;

    // E stage fill: thread covers float4 idx {tid, 256+tid} of 512 per stage
    const int le0 = tid >> 2,         kq0 = tid & 3;
    const int le1 = (256 + tid) >> 2, kq1 = (256 + tid) & 3;

    float4 pf0, pf1;
    pf0 = *reinterpret_cast<const float4*>(e + (size_t)(e0 + le0) * EDGE_DIM + kq0 * 4);
    pf1 = *reinterpret_cast<const float4*>(e + (size_t)(e0 + le1) * EDGE_DIM + kq1 * 4);
    Esh[0][kq0 * 4 + 0][le0] = pf0.x; Esh[0][kq0 * 4 + 1][le0] = pf0.y;
    Esh[0][kq0 * 4 + 2][le0] = pf0.z; Esh[0][kq0 * 4 + 3][le0] = pf0.w;
    Esh[0][kq1 * 4 + 0][le1] = pf1.x; Esh[0][kq1 * 4 + 1][le1] = pf1.y;
    Esh[0][kq1 * 4 + 2][le1] = pf1.z; Esh[0][kq1 * 4 + 3][le1] = pf1.w;
    __syncthreads();

#pragma unroll 1
    for (int s = 0; s < 4; ++s) {
        const int cur = s & 1;
        if (s < 3) {  // prefetch next stage into registers
            pf0 = *reinterpret_cast<const float4*>(
                e + (size_t)(e0 + le0) * EDGE_DIM + (s + 1) * 16 + kq0 * 4);
            pf1 = *reinterpret_cast<const float4*>(
                e + (size_t)(e0 + le1) * EDGE_DIM + (s + 1) * 16 + kq1 * 4);
        }

#pragma unroll
        for (int k = 0; k < 16; ++k) {
            int kk = s * 16 + k;
            u64 w2[4];
            {
                ulonglong2 wa = *reinterpret_cast<const ulonglong2*>(&Wd[kk][tx * 4]);
                ulonglong2 wb = *reinterpret_cast<const ulonglong2*>(&Wd[kk][tx * 4 + 2]);
                w2[0] = wa.x; w2[1] = wa.y; w2[2] = wb.x; w2[3] = wb.y;
            }
            u64 ev[4];
            {
                ulonglong2 ea = *reinterpret_cast<const ulonglong2*>(&Esh[cur][k][ty * 8]);
                ulonglong2 eb = *reinterpret_cast<const ulonglong2*>(&Esh[cur][k][ty * 8 + 4]);
                ev[0] = ea.x; ev[1] = ea.y; ev[2] = eb.x; ev[3] = eb.y;
            }
#pragma unroll
            for (int p = 0; p < 4; ++p)
#pragma unroll
                for (int j = 0; j < 4; ++j)
                    fma2(acc[p][j], ev[p], w2[j]);
        }

        if (s < 3) {
            const int nxt = cur ^ 1;
            // write other buffer: safe w.r.t. warps still reading 'cur'
            Esh[nxt][kq0 * 4 + 0][le0] = pf0.x; Esh[nxt][kq0 * 4 + 1][le0] = pf0.y;
            Esh[nxt][kq0 * 4 + 2][le0] = pf0.z; Esh[nxt][kq0 * 4 + 3][le0] = pf0.w;
            Esh[nxt][kq1 * 4 + 0][le1] = pf1.x; Esh[nxt][kq1 * 4 + 1][le1] = pf1.y;
            Esh[nxt][kq1 * 4 + 2][le1] = pf1.z; Esh[nxt][kq1 * 4 + 3][le1] = pf1.w;
            __syncthreads();
        }
    }

    // Epilogue: gather hu[src], hw[tgt] (L2-resident), coalesced float4 stores.
#pragma unroll
    for (int p = 0; p < 4; ++p) {
        int ea = e0 + ty * 8 + 2 * p;   // edge pair (ea, ea+1)
        int sa = fetch_idx(ei32, is64, (size_t)ea);
        int ta = fetch_idx(ei32, is64, (size_t)N_EDGES + ea);
        int sb = fetch_idx(ei32, is64, (size_t)ea + 1);
        int tb = fetch_idx(ei32, is64, (size_t)N_EDGES + ea + 1);

        float2 v0 = unpack2(acc[p][0]), v1 = unpack2(acc[p][1]);
        float2 v2 = unpack2(acc[p][2]), v3 = unpack2(acc[p][3]);

        float4 A = *reinterpret_cast<const float4*>(g_HU + (size_t)sa * OUT_DIM + oh + tx * 4);
        float4 B = *reinterpret_cast<const float4*>(g_HW + (size_t)ta * OUT_DIM + oh + tx * 4);
        float4 C = *reinterpret_cast<const float4*>(g_HU + (size_t)sb * OUT_DIM + oh + tx * 4);
        float4 D = *reinterpret_cast<const float4*>(g_HW + (size_t)tb * OUT_DIM + oh + tx * 4);

        *reinterpret_cast<float4*>(out + (size_t)ea * OUT_DIM + oh + tx * 4) =
            make_float4(v0.x + A.x + B.x, v1.x + A.y + B.y,
                        v2.x + A.z + B.z, v3.x + A.w + B.w);
        *reinterpret_cast<float4*>(out + (size_t)(ea + 1) * OUT_DIM + oh + tx * 4) =
            make_float4(v0.y + C.x + D.x, v1.y + C.y + D.y,
                        v2.y + C.z + D.z, v3.y + C.w + D.w);
    }
}

extern "C" void kernel_launch(void* const* d_in, const int* in_sizes, int n_in,
                              void* d_out, int out_size)
{
    const float* h   = (const float*)d_in[0];       // [50000,128]
    const float* e   = (const float*)d_in[1];       // [800000,64]
    const int*   ei  = (const int*)d_in[2];         // [2,800000]
    const float* We  = (const float*)d_in[3];       // [128,64]
    const float* Whu = (const float*)d_in[4];       // [128,128]
    const float* Whw = (const float*)d_in[5];       // [128,128]
    float*       out = (float*)d_out;               // [800000,128]

    dim3 ngrid((N_NODES + 127) / 128, 2);
    node_proj_kernel<<<ngrid, 256>>>(h, Whu, Whw, ei);

    // Edge work split into two launches (profile landing + identical math).
    const int half = (N_EDGES / 128) / 2;           // 3125 tiles each
    dim3 egrid(half, 2);
    edge_kernel<<<egrid, 256>>>(e, ei, We, out, 0);
    edge_kernel<<<egrid, 256>>>(e, ei, We, out, half);
}

// round 8
// speedup vs baseline: 1.5407x; 1.5407x over previous
#include <cuda_runtime.h>
#include <cstdint>

#define N_NODES 50000
#define N_EDGES 800000
#define IN_DIM  128
#define OUT_DIM 128
#define EDGE_DIM 64
#define TPB_TILES 10            // edge tiles per block
#define EGRID_X   625           // 625 * 10 * 128 = 800000

typedef unsigned long long u64;

// Scratch for node projections (allocation-free per harness rules).
__device__ __align__(16) float g_HU[(size_t)N_NODES * OUT_DIM];
__device__ __align__(16) float g_HW[(size_t)N_NODES * OUT_DIM];
__device__ int g_idx_is64;

__device__ __forceinline__ u64 pack2(float lo, float hi) {
    u64 r; asm("mov.b64 %0, {%1, %2};" : "=l"(r) : "f"(lo), "f"(hi)); return r;
}
__device__ __forceinline__ void fma2(u64& d, u64 a, u64 b) {
    asm("fma.rn.f32x2 %0, %1, %2, %3;" : "=l"(d) : "l"(a), "l"(b), "l"(d));
}
__device__ __forceinline__ float2 unpack2(u64 v) {
    float2 f; asm("mov.b64 {%0, %1}, %2;" : "=f"(f.x), "=f"(f.y) : "l"(v)); return f;
}

__device__ __forceinline__ int fetch_idx(const int* __restrict__ ei32,
                                         int is64, size_t pos) {
    int v = is64 ? ei32[2 * pos] : ei32[pos];
    v = v < 0 ? 0 : (v >= N_NODES ? N_NODES - 1 : v);
    return v;
}

// ---------------------------------------------------------------------------
// Node projection (both W_hu and W_hw via blockIdx.y) — proven kernel.
// Block (0,0) also performs index-dtype detection (edge launches after).
// ---------------------------------------------------------------------------
__global__ __launch_bounds__(256, 2)
void node_proj_kernel(const float* __restrict__ h,
                      const float* __restrict__ Whu,
                      const float* __restrict__ Whw,
                      const int* __restrict__ ei32)
{
    __shared__ __align__(16) float Wsh[32][132];
    __shared__ __align__(16) float Hsh[32][132];

    if (blockIdx.x == 0 && blockIdx.y == 0 && threadIdx.x == 0) {
        int all_zero = 1;
        for (int i = 0; i < 256; ++i)
            if (ei32[2 * i + 1] != 0) { all_zero = 0; break; }
        g_idx_is64 = all_zero;
    }

    const float* __restrict__ W   = blockIdx.y ? Whw : Whu;
    float*       __restrict__ dst = blockIdx.y ? g_HW : g_HU;

    const int tid = threadIdx.x;
    const int tx  = tid & 31;
    const int ty  = tid >> 5;
    const int n0  = blockIdx.x * 128;

    u64 acc[8][4];
#pragma unroll
    for (int p = 0; p < 8; ++p)
#pragma unroll
        for (int j = 0; j < 4; ++j) acc[p][j] = 0ULL;

#pragma unroll 1
    for (int s = 0; s < 4; ++s) {
        __syncthreads();
#pragma unroll
        for (int it = 0; it < 4; ++it) {
            int idx = it * 256 + tid;
            int o   = idx >> 3;
            int kq  = idx & 7;
            float4 w = *reinterpret_cast<const float4*>(W + (size_t)o * IN_DIM + s * 32 + kq * 4);
            Wsh[kq * 4 + 0][o] = w.x; Wsh[kq * 4 + 1][o] = w.y;
            Wsh[kq * 4 + 2][o] = w.z; Wsh[kq * 4 + 3][o] = w.w;
        }
#pragma unroll
        for (int it = 0; it < 4; ++it) {
            int idx = it * 256 + tid;
            int ln  = idx >> 3;
            int kq  = idx & 7;
            int n   = n0 + ln;
            float4 v = make_float4(0.f, 0.f, 0.f, 0.f);
            if (n < N_NODES)
                v = *reinterpret_cast<const float4*>(h + (size_t)n * IN_DIM + s * 32 + kq * 4);
            Hsh[kq * 4 + 0][ln] = v.x; Hsh[kq * 4 + 1][ln] = v.y;
            Hsh[kq * 4 + 2][ln] = v.z; Hsh[kq * 4 + 3][ln] = v.w;
        }
        __syncthreads();

#pragma unroll
        for (int k = 0; k < 32; ++k) {
            float4 w = *reinterpret_cast<const float4*>(&Wsh[k][tx * 4]);
            u64 w2[4];
            w2[0] = pack2(w.x, w.x); w2[1] = pack2(w.y, w.y);
            w2[2] = pack2(w.z, w.z); w2[3] = pack2(w.w, w.w);
            u64 ev[8];
#pragma unroll
            for (int q = 0; q < 4; ++q) {
                ulonglong2 ep = *reinterpret_cast<const ulonglong2*>(&Hsh[k][ty * 16 + q * 4]);
                ev[2 * q] = ep.x; ev[2 * q + 1] = ep.y;
            }
#pragma unroll
            for (int p = 0; p < 8; ++p)
#pragma unroll
                for (int j = 0; j < 4; ++j)
                    fma2(acc[p][j], ev[p], w2[j]);
        }
    }

#pragma unroll
    for (int p = 0; p < 8; ++p) {
        int na = n0 + ty * 16 + 2 * p;
        float2 v0 = unpack2(acc[p][0]), v1 = unpack2(acc[p][1]);
        float2 v2 = unpack2(acc[p][2]), v3 = unpack2(acc[p][3]);
        if (na < N_NODES)
            *reinterpret_cast<float4*>(dst + (size_t)na * OUT_DIM + tx * 4) =
                make_float4(v0.x, v1.x, v2.x, v3.x);
        if (na + 1 < N_NODES)
            *reinterpret_cast<float4*>(dst + (size_t)(na + 1) * OUT_DIM + tx * 4) =
                make_float4(v0.y, v1.y, v2.y, v3.y);
    }
}

// ---------------------------------------------------------------------------
// Fused edge kernel v4: multi-tile persistent blocks.
// Grid 625 x 2; each block: 64-out half (blockIdx.y), 10 consecutive
// 128-edge tiles. We fill once per block. Flattened 40-stage pipeline,
// double-buffered Esh, ONE barrier per stage, register prefetch of next
// stage (crossing tile boundaries). Mainloop identical to R6 (conflict-free).
// ---------------------------------------------------------------------------
__global__ __launch_bounds__(256, 3)
void edge_kernel(const float* __restrict__ e,
                 const int* __restrict__ ei32,
                 const float* __restrict__ We,
                 float* __restrict__ out)
{
    __shared__ __align__(16) float Wsh[EDGE_DIM][68];   // [k][o-half]  ~17.4KB
    __shared__ __align__(16) float Esh[2][16][132];     // double buf   ~16.9KB

    const int tid  = threadIdx.x;
    const int tx   = tid & 15;   // outs: oh + tx*4 .. +3
    const int ty   = tid >> 4;   // edges: ty*8 .. ty*8+7
    const int oh   = blockIdx.y * 64;
    const int is64 = g_idx_is64;

    // One-time W fill (conflict-free mapping; LDG mostly L2-hits).
#pragma unroll
    for (int it = 0; it < 4; ++it) {
        int idx = it * 256 + tid;       // 0..1023
        int o   = idx & 63;
        int kq  = idx >> 6;             // 0..15
        float4 w = *reinterpret_cast<const float4*>(
            We + (size_t)(oh + o) * EDGE_DIM + kq * 4);
        Wsh[kq * 4 + 0][o] = w.x;
        Wsh[kq * 4 + 1][o] = w.y;
        Wsh[kq * 4 + 2][o] = w.z;
        Wsh[kq * 4 + 3][o] = w.w;
    }

    // E stage fill assignment: thread covers float4 idx {tid, 256+tid} of 512
    const int le0 = tid >> 2,         kq0 = tid & 3;
    const int le1 = (256 + tid) >> 2, kq1 = (256 + tid) & 3;

    const int t0 = blockIdx.x * TPB_TILES;
    const int NS = 4 * TPB_TILES;            // stages total

    // Prefetch + fill stage 0 of tile 0 into buffer 0.
    float4 pf0 = *reinterpret_cast<const float4*>(
        e + (size_t)(t0 * 128 + le0) * EDGE_DIM + kq0 * 4);
    float4 pf1 = *reinterpret_cast<const float4*>(
        e + (size_t)(t0 * 128 + le1) * EDGE_DIM + kq1 * 4);
    Esh[0][kq0 * 4 + 0][le0] = pf0.x; Esh[0][kq0 * 4 + 1][le0] = pf0.y;
    Esh[0][kq0 * 4 + 2][le0] = pf0.z; Esh[0][kq0 * 4 + 3][le0] = pf0.w;
    Esh[0][kq1 * 4 + 0][le1] = pf1.x; Esh[0][kq1 * 4 + 1][le1] = pf1.y;
    Esh[0][kq1 * 4 + 2][le1] = pf1.z; Esh[0][kq1 * 4 + 3][le1] = pf1.w;
    __syncthreads();

    u64 acc[4][4];

#pragma unroll 1
    for (int gs = 0; gs < NS; ++gs) {
        const int cur  = gs & 1;
        const int tile = gs >> 2;
        const int s    = gs & 3;

        // prefetch next stage (possibly next tile's stage 0)
        if (gs + 1 < NS) {
            const int nt = (gs + 1) >> 2, nss = (gs + 1) & 3;
            pf0 = *reinterpret_cast<const float4*>(
                e + (size_t)((t0 + nt) * 128 + le0) * EDGE_DIM + nss * 16 + kq0 * 4);
            pf1 = *reinterpret_cast<const float4*>(
                e + (size_t)((t0 + nt) * 128 + le1) * EDGE_DIM + nss * 16 + kq1 * 4);
        }

        if (s == 0) {
#pragma unroll
            for (int p = 0; p < 4; ++p)
#pragma unroll
                for (int j = 0; j < 4; ++j) acc[p][j] = 0ULL;
        }

        // ---- 16 k-steps on Esh[cur] (R6-proven inner loop) ----
#pragma unroll
        for (int k = 0; k < 16; ++k) {
            int kk = s * 16 + k;
            float4 w = *reinterpret_cast<const float4*>(&Wsh[kk][tx * 4]);
            u64 w2[4];
            w2[0] = pack2(w.x, w.x); w2[1] = pack2(w.y, w.y);
            w2[2] = pack2(w.z, w.z); w2[3] = pack2(w.w, w.w);
            u64 ev[4];
            {
                ulonglong2 ea = *reinterpret_cast<const ulonglong2*>(&Esh[cur][k][ty * 8]);
                ulonglong2 eb = *reinterpret_cast<const ulonglong2*>(&Esh[cur][k][ty * 8 + 4]);
                ev[0] = ea.x; ev[1] = ea.y; ev[2] = eb.x; ev[3] = eb.y;
            }
#pragma unroll
            for (int p = 0; p < 4; ++p)
#pragma unroll
                for (int j = 0; j < 4; ++j)
                    fma2(acc[p][j], ev[p], w2[j]);
        }

        // ---- tile finished: gather + store epilogue (no smem touched) ----
        if (s == 3) {
            const int eb0 = (t0 + tile) * 128;
#pragma unroll
            for (int p = 0; p < 4; ++p) {
                int ea = eb0 + ty * 8 + 2 * p;
                int sa = fetch_idx(ei32, is64, (size_t)ea);
                int ta = fetch_idx(ei32, is64, (size_t)N_EDGES + ea);
                int sb = fetch_idx(ei32, is64, (size_t)ea + 1);
                int tb = fetch_idx(ei32, is64, (size_t)N_EDGES + ea + 1);

                float2 v0 = unpack2(acc[p][0]), v1 = unpack2(acc[p][1]);
                float2 v2 = unpack2(acc[p][2]), v3 = unpack2(acc[p][3]);

                float4 A = *reinterpret_cast<const float4*>(g_HU + (size_t)sa * OUT_DIM + oh + tx * 4);
                float4 B = *reinterpret_cast<const float4*>(g_HW + (size_t)ta * OUT_DIM + oh + tx * 4);
                float4 C = *reinterpret_cast<const float4*>(g_HU + (size_t)sb * OUT_DIM + oh + tx * 4);
                float4 D = *reinterpret_cast<const float4*>(g_HW + (size_t)tb * OUT_DIM + oh + tx * 4);

                *reinterpret_cast<float4*>(out + (size_t)ea * OUT_DIM + oh + tx * 4) =
                    make_float4(v0.x + A.x + B.x, v1.x + A.y + B.y,
                                v2.x + A.z + B.z, v3.x + A.w + B.w);
                *reinterpret_cast<float4*>(out + (size_t)(ea + 1) * OUT_DIM + oh + tx * 4) =
                    make_float4(v0.y + C.x + D.x, v1.y + C.y + D.y,
                                v2.y + C.z + D.z, v3.y + C.w + D.w);
            }
        }

        // ---- publish prefetched stage into the other buffer ----
        if (gs + 1 < NS) {
            const int nxt = cur ^ 1;
            Esh[nxt][kq0 * 4 + 0][le0] = pf0.x; Esh[nxt][kq0 * 4 + 1][le0] = pf0.y;
            Esh[nxt][kq0 * 4 + 2][le0] = pf0.z; Esh[nxt][kq0 * 4 + 3][le0] = pf0.w;
            Esh[nxt][kq1 * 4 + 0][le1] = pf1.x; Esh[nxt][kq1 * 4 + 1][le1] = pf1.y;
            Esh[nxt][kq1 * 4 + 2][le1] = pf1.z; Esh[nxt][kq1 * 4 + 3][le1] = pf1.w;
            __syncthreads();
        }
    }
}

extern "C" void kernel_launch(void* const* d_in, const int* in_sizes, int n_in,
                              void* d_out, int out_size)
{
    const float* h   = (const float*)d_in[0];       // [50000,128]
    const float* e   = (const float*)d_in[1];       // [800000,64]
    const int*   ei  = (const int*)d_in[2];         // [2,800000]
    const float* We  = (const float*)d_in[3];       // [128,64]
    const float* Whu = (const float*)d_in[4];       // [128,128]
    const float* Whw = (const float*)d_in[5];       // [128,128]
    float*       out = (float*)d_out;               // [800000,128]

    dim3 ngrid((N_NODES + 127) / 128, 2);
    node_proj_kernel<<<ngrid, 256>>>(h, Whu, Whw, ei);

    dim3 egrid(EGRID_X, 2);
    edge_kernel<<<egrid, 256>>>(e, ei, We, out);
}